// round 12
// baseline (speedup 1.0000x reference)
#include <cuda_runtime.h>
#include <math.h>

typedef unsigned long long u64;

// ---- packed f32x2 helpers (sm_103a; ptxas won't auto-fuse) ----
__device__ __forceinline__ u64 pack2(float x, float y) {
    u64 r; asm("mov.b64 %0, {%1, %2};" : "=l"(r) : "f"(x), "f"(y)); return r;
}
__device__ __forceinline__ u64 fma2(u64 a, u64 b, u64 c) {
    u64 d; asm("fma.rn.f32x2 %0, %1, %2, %3;" : "=l"(d) : "l"(a), "l"(b), "l"(c)); return d;
}
__device__ __forceinline__ u64 mul2(u64 a, u64 b) {
    u64 d; asm("mul.rn.f32x2 %0, %1, %2;" : "=l"(d) : "l"(a), "l"(b)); return d;
}
__device__ __forceinline__ u64 add2(u64 a, u64 b) {
    u64 d; asm("add.rn.f32x2 %0, %1, %2;" : "=l"(d) : "l"(a), "l"(b)); return d;
}
__device__ __forceinline__ float2 unpack2(u64 v) {
    float x, y; asm("mov.b64 {%0, %1}, %2;" : "=f"(x), "=f"(y) : "l"(v)); return make_float2(x, y);
}

#define MAXB 8192
#define TILE 128          // images per tile
#define NT   256          // threads per block (8 warps, 2 row-groups)

// per-(row-group, image) partials: [0:14B) sum, [14B:28B) sumsq, [28B:42B) qdot
__device__ float g_part[3 * 14 * MAXB];
// per-image-tile completion counters (finisher resets to 0 -> replay-safe)
__device__ int g_cnt[(MAXB + TILE - 1) / TILE];

// Sparse trig-basis contraction: column m of the half->full angle map has
// exactly 4 nonzeros at pair-indices CAA[m][q] with signs CSG[m][q].
__constant__ int   CAA[9][4] = {
    {0,5,10,15}, {0,5,10,15}, {1,4,11,14}, {0,5,10,15}, {0,5,10,15},
    {1,4,11,14}, {2,7,8,13}, {2,7,8,13}, {3,6,9,12}};
__constant__ float CSG[9][4] = {
    {1,1,1,1}, {1,-1,1,-1}, {1,1,1,1}, {1,1,-1,-1}, {1,-1,-1,1},
    {1,1,-1,-1}, {1,1,1,1}, {1,-1,1,-1}, {1,1,1,1}};

// triangular row base: base[r] = r*(33-r)/2
__constant__ int TRI_BASE[17] = {0,16,31,45,58,70,81,91,100,108,115,121,126,130,133,135,136};

// ---------------------------------------------------------------------------
// Single fused kernel. Block = 128 images x TWO patch-row groups:
// warps 0-3 handle rg=2*gy, warps 4-7 handle rg=2*gy+1. The base-matrix
// prologue runs once per block (amortized over both row groups) with 256
// threads; 8 warps per barrier hide latency far better than 4.
// grid = (B/128, 7) = 448 blocks -> one wave on 148 SMs.
// ---------------------------------------------------------------------------
__global__ void __launch_bounds__(NT, 4) fused_kernel(
    const float* __restrict__ x,
    const float* __restrict__ U_re, const float* __restrict__ U_im,
    const float* __restrict__ w_cls,
    const float* __restrict__ w_in,  const float* __restrict__ b_in,
    const float* __restrict__ scale_in, const float* __restrict__ shift_in,
    const float* __restrict__ Wc,    const float* __restrict__ bc,
    const float* __restrict__ scalec, const float* __restrict__ shiftc,
    const float* __restrict__ w_out, const float* __restrict__ b_out,
    const float* __restrict__ b_cls,
    float* __restrict__ out, int B, int Lc)
{
    __shared__ float xs[2 * TILE * 29];             // per-rg 7-patch chunks, odd stride
    __shared__ __align__(16) u64 Ms[28 * 54];       // 12.1 KB; prologue scratch aliased
    __shared__ float Nbs[368];                      // [(w*9+m)*10 + n], n=9 padded 0
    __shared__ int s_old;

    float* scr = (float*)Ms;                        // 1512 u64 = 3024 floats available
    float* urs = scr;                               // 256
    float* uis = scr + 256;                         // 256
    float* Hs  = scr + 512;                         // [w*256 + r*16 + c]  (1024)
    float* T1  = scr + 1536;                        // [w*144 + m*16 + bb] (576) -> 2112 total

    const int t   = threadIdx.x;
    const int bx  = blockIdx.x;
    const int gy  = blockIdx.y;                     // 0..6 (rg pair)
    const int b0  = bx * TILE;
    const int tl  = t & 127;                        // image lane
    const int rgl = t >> 7;                         // 0/1 within pair
    const int rg  = 2 * gy + rgl;
    const int nimg = min(TILE, B - b0);

    for (int i = t; i < 256; i += NT) { urs[i] = U_re[i]; uis[i] = U_im[i]; }
    __syncthreads();

    // ---- P2: H_w[r][c] (symmetric, 136 unique entries, Walsh signs) ----
    if (t < 136) {
        const int e = t;
        int r = (int)((33.0f - sqrtf(1089.0f - 8.0f * (float)e)) * 0.5f);
        if (r > 15) r = 15;
        while (e < TRI_BASE[r]) r--;
        while (e >= TRI_BASE[r + 1]) r++;
        const int c = r + (e - TRI_BASE[r]);
        float h0 = 0.f, h1 = 0.f, h2 = 0.f, h3 = 0.f;
        #pragma unroll
        for (int k = 0; k < 16; k++) {
            float pr = urs[k * 16 + r] * urs[k * 16 + c]
                     + uis[k * 16 + r] * uis[k * 16 + c];
            h0 += (k & 8) ? -pr : pr;
            h1 += (k & 4) ? -pr : pr;
            h2 += (k & 2) ? -pr : pr;
            h3 += (k & 1) ? -pr : pr;
        }
        Hs[0 * 256 + r * 16 + c] = h0;  Hs[0 * 256 + c * 16 + r] = h0;
        Hs[1 * 256 + r * 16 + c] = h1;  Hs[1 * 256 + c * 16 + r] = h1;
        Hs[2 * 256 + r * 16 + c] = h2;  Hs[2 * 256 + c * 16 + r] = h2;
        Hs[3 * 256 + r * 16 + c] = h3;  Hs[3 * 256 + c * 16 + r] = h3;
    }
    __syncthreads();

    // ---- P3: contract (a1,a2) -> m (4 sparse terms each) ----
    for (int e = t; e < 576; e += NT) {
        const int w = e / 144, rem = e % 144, m = rem >> 4, bb = rem & 15;
        const int b1 = bb >> 2, b2 = bb & 3;
        float acc = 0.f;
        #pragma unroll
        for (int q = 0; q < 4; q++) {
            const int aa = CAA[m][q], a1 = aa >> 2, a2 = aa & 3;
            acc = fmaf(CSG[m][q], Hs[w * 256 + (4 * a1 + b1) * 16 + 4 * a2 + b2], acc);
        }
        T1[w * 144 + m * 16 + bb] = acc;
    }
    __syncthreads();

    // ---- P4: contract (b1,b2) -> n, scale 1/16, pad n=9 with 0 ----
    for (int e = t; e < 360; e += NT) {
        const int w = e / 90, rem = e % 90, m = rem / 10, n = rem % 10;
        float acc = 0.f;
        if (n < 9) {
            #pragma unroll
            for (int q = 0; q < 4; q++)
                acc = fmaf(CSG[n][q], T1[w * 144 + m * 16 + CAA[n][q]], acc);
            acc *= 0.0625f;
        }
        Nbs[e] = acc;
    }
    __syncthreads();

    // ---- P5: fold w_cls into 28 per-patch matrices (both row groups) ----
    // (overwrites scr region; Nbs is separate)
    for (int e = t; e < 28 * 45; e += NT) {
        const int pc2 = e / 45, r = e % 45, m = r / 5, np = r % 5;
        const int rgf = 2 * gy + pc2 / 14, patch = pc2 % 14;
        const float* wc = w_cls + 1 + 4 * (rgf * 14 + patch);
        float lo = 0.f, hi = 0.f;
        #pragma unroll
        for (int w = 0; w < 4; w++) {
            const float wcv = __ldg(wc + w);
            lo = fmaf(wcv, Nbs[(w * 9 + m) * 10 + 2 * np],     lo);
            hi = fmaf(wcv, Nbs[(w * 9 + m) * 10 + 2 * np + 1], hi);
        }
        Ms[pc2 * 54 + m * 6 + np] = pack2(lo, hi);
    }

    // ---- main loop: two 7-patch chunks; 9x9 bilinear form per patch ----
    u64 s2 = 0ull, sq2 = 0ull;                      // packed mean/sumsq partials
    float C = 0.f;
    const float* xt = xs + rgl * (TILE * 29) + tl * 29;

    #pragma unroll 1
    for (int half = 0; half < 2; half++) {
        __syncthreads();                            // Ms ready (h=0) / xs reuse safe (h=1)
        const int cb = half * 14;
        // stage: both rgs, 28 floats per image each
        for (int i = t; i < 2 * TILE * 28; i += NT) {
            const int rgs = i / (TILE * 28), rem = i % (TILE * 28);
            const int img = rem / 28, c = rem % 28;
            if (img < nimg) {
                const int rgf = 2 * gy + rgs;
                const int src = rgf * 56 + ((c < 14) ? (cb + c) : (28 + cb + (c - 14)));
                xs[rgs * (TILE * 29) + img * 29 + c] = x[(size_t)(b0 + img) * 784 + src];
            }
        }
        __syncthreads();

        if (tl < nimg) {
            #pragma unroll 1
            for (int pcl = 0; pcl < 7; pcl++) {
                const float p0 = xt[2 * pcl],      p1 = xt[2 * pcl + 1];
                const float p2 = xt[14 + 2 * pcl], p3 = xt[15 + 2 * pcl];
                const u64 x01 = pack2(p0, p1), x23 = pack2(p2, p3);
                s2  = add2(s2, add2(x01, x23));
                sq2 = fma2(x01, x01, fma2(x23, x23, sq2));

                float sn0, cs0, sn1, cs1, sn2, cs2, sn3, cs3;
                __sincosf(p0, &sn0, &cs0);
                __sincosf(p1, &sn1, &cs1);
                __sincosf(p2, &sn2, &cs2);
                __sincosf(p3, &sn3, &cs3);

                // u = (1,c1,s1,c0,c0c1,c0s1,s0,s0c1,s0s1); v likewise on p2,p3
                const float u4 = cs0 * cs1, u5 = cs0 * sn1, u7 = sn0 * cs1, u8 = sn0 * sn1;
                const float v4 = cs2 * cs3, v5 = cs2 * sn3, v7 = sn2 * cs3, v8 = sn2 * sn3;
                const u64 vp0 = pack2(1.f, cs3), vp1 = pack2(sn3, cs2);
                const u64 vp2 = pack2(v4, v5),   vp3 = pack2(sn2, v7);
                const u64 vp4 = pack2(v8, 0.f);
                const float us[9] = {1.f, cs1, sn1, cs0, u4, u5, sn0, u7, u8};

                const u64* Mp = Ms + (rgl * 14 + 7 * half + pcl) * 54;
                u64 c2a = 0ull, c2b = 0ull;
                #pragma unroll
                for (int m = 0; m < 9; m++) {
                    const ulonglong2* row = (const ulonglong2*)(Mp + m * 6);
                    const ulonglong2 e01 = row[0];     // np 0,1 (broadcast LDS.128)
                    const ulonglong2 e23 = row[1];     // np 2,3
                    u64 y = mul2(e01.x, vp0);
                    y = fma2(e01.y, vp1, y);
                    y = fma2(e23.x, vp2, y);
                    y = fma2(e23.y, vp3, y);
                    y = fma2(Mp[m * 6 + 4], vp4, y);   // np 4 (v8, 0)
                    const u64 uu = pack2(us[m], us[m]);
                    if (m & 1) c2b = fma2(y, uu, c2b);
                    else       c2a = fma2(y, uu, c2a);
                }
                const float2 cc = unpack2(add2(c2a, c2b));
                C += cc.x + cc.y;
            }
        }
    }

    if (tl < nimg) {
        const float2 sv = unpack2(s2);
        const float2 qv = unpack2(sq2);
        const int b = b0 + tl;
        g_part[rg * B + b]        = sv.x + sv.y;
        g_part[(14 + rg) * B + b] = qv.x + qv.y;
        g_part[(28 + rg) * B + b] = C;
    }

    // ---- last-block-done finisher (7 blocks per image tile) ----
    __threadfence();
    __syncthreads();
    if (t == 0) s_old = atomicAdd(&g_cnt[bx], 1);
    __syncthreads();
    if (s_old != 6) return;

    if (t == 0) g_cnt[bx] = 0;        // reset for next launch / graph replay
    if (t >= nimg) return;            // threads 0..nimg-1 finish images

    const int b = b0 + t;
    float S = 0.f, Q = 0.f, Cq = 0.f;
    #pragma unroll
    for (int r = 0; r < 14; r++) {
        S  += g_part[r * B + b];
        Q  += g_part[(14 + r) * B + b];
        Cq += g_part[(28 + r) * B + b];
    }
    float mean = S * (1.f / 784.f);
    float var  = (Q - S * S * (1.f / 784.f)) * (1.f / 783.f);   // ddof=1
    float sd   = sqrtf(fmaxf(var, 0.f));
    float h0 = tanhf(mean * w_in[0] + sd * w_in[1] + b_in[0]) * scale_in[0] + shift_in[0];
    float h1 = tanhf(mean * w_in[2] + sd * w_in[3] + b_in[1]) * scale_in[1] + shift_in[1];
    for (int l = 0; l < Lc; l++) {
        float n0 = tanhf(h0 * Wc[l*4+0] + h1 * Wc[l*4+1] + bc[l*2+0]) * scalec[l*2+0] + shiftc[l*2+0];
        float n1 = tanhf(h0 * Wc[l*4+2] + h1 * Wc[l*4+3] + bc[l*2+1]) * scalec[l*2+1] + shiftc[l*2+1];
        h0 = n0; h1 = n1;
    }
    float cls   = h0 * w_out[0] + h1 * w_out[1] + b_out[0];
    float logit = b_cls[0] + cls * w_cls[0] + Cq;
    out[b] = 1.f / (1.f + __expf(-logit));
}

extern "C" void kernel_launch(void* const* d_in, const int* in_sizes, int n_in,
                              void* d_out, int out_size)
{
    const float* x        = (const float*)d_in[0];
    const float* w_in     = (const float*)d_in[1];
    const float* b_in     = (const float*)d_in[2];
    const float* scale_in = (const float*)d_in[3];
    const float* shift_in = (const float*)d_in[4];
    const float* Wc       = (const float*)d_in[5];
    const float* bc       = (const float*)d_in[6];
    const float* scalec   = (const float*)d_in[7];
    const float* shiftc   = (const float*)d_in[8];
    const float* w_out    = (const float*)d_in[9];
    const float* b_out    = (const float*)d_in[10];
    const float* U_re     = (const float*)d_in[11];
    const float* U_im     = (const float*)d_in[12];
    const float* w_cls    = (const float*)d_in[13];
    const float* b_cls    = (const float*)d_in[14];
    float* out = (float*)d_out;

    const int B  = in_sizes[0] / 784;   // (B,1,28,28)
    const int Lc = in_sizes[5] / 4;     // (L,2,2)

    dim3 grid((B + TILE - 1) / TILE, 7);
    fused_kernel<<<grid, NT>>>(x, U_re, U_im, w_cls,
                               w_in, b_in, scale_in, shift_in,
                               Wc, bc, scalec, shiftc, w_out, b_out,
                               b_cls, out, B, Lc);
}

// round 13
// speedup vs baseline: 1.0738x; 1.0738x over previous
#include <cuda_runtime.h>
#include <math.h>

typedef unsigned long long u64;

// ---- packed f32x2 helpers (sm_103a; ptxas won't auto-fuse) ----
__device__ __forceinline__ u64 pack2(float x, float y) {
    u64 r; asm("mov.b64 %0, {%1, %2};" : "=l"(r) : "f"(x), "f"(y)); return r;
}
__device__ __forceinline__ u64 fma2(u64 a, u64 b, u64 c) {
    u64 d; asm("fma.rn.f32x2 %0, %1, %2, %3;" : "=l"(d) : "l"(a), "l"(b), "l"(c)); return d;
}
__device__ __forceinline__ u64 mul2(u64 a, u64 b) {
    u64 d; asm("mul.rn.f32x2 %0, %1, %2;" : "=l"(d) : "l"(a), "l"(b)); return d;
}
__device__ __forceinline__ u64 add2(u64 a, u64 b) {
    u64 d; asm("add.rn.f32x2 %0, %1, %2;" : "=l"(d) : "l"(a), "l"(b)); return d;
}
__device__ __forceinline__ float2 unpack2(u64 v) {
    float x, y; asm("mov.b64 {%0, %1}, %2;" : "=f"(x), "=f"(y) : "l"(v)); return make_float2(x, y);
}

#define MAXB 8192
#define TILE 128

// per-(halfgroup, image) partials: rows 0..27 = sum, 28..55 = sumsq, 56..83 = qdot
__device__ float g_part[3 * 28 * MAXB];
// per-image-tile completion counters (finisher resets to 0 -> replay-safe)
__device__ int g_cnt[(MAXB + TILE - 1) / TILE];

// Sparse trig-basis contraction: column m of the half->full angle map has
// exactly 4 nonzeros at pair-indices CAA[m][q] with signs CSG[m][q].
__constant__ int   CAA[9][4] = {
    {0,5,10,15}, {0,5,10,15}, {1,4,11,14}, {0,5,10,15}, {0,5,10,15},
    {1,4,11,14}, {2,7,8,13}, {2,7,8,13}, {3,6,9,12}};
__constant__ float CSG[9][4] = {
    {1,1,1,1}, {1,-1,1,-1}, {1,1,1,1}, {1,1,-1,-1}, {1,-1,-1,1},
    {1,1,-1,-1}, {1,1,1,1}, {1,-1,1,-1}, {1,1,1,1}};

// triangular row base: base[r] = r*16 - r(r-1)/2
__constant__ int TRI_BASE[17] = {0,16,31,45,58,70,81,91,100,108,115,121,126,130,133,135,136};

// ---------------------------------------------------------------------------
// Single fused kernel, fine-grained: block = 128 images x SEVEN patches
// (half a patch-row group). grid = (B/128, 28) = 1792 blocks -> 8 blocks/SM
// (smem 23.3 KB, regs 64) = 32 warps/SM residency, double R8's cap.
// Prologue rebuilds the 4 base matrices (phase-aliased smem) and folds
// w_cls into just this block's 7 bilinear forms. Last of the 28 blocks per
// image tile runs the classical MLP + sigmoid.
// ---------------------------------------------------------------------------
__global__ void __launch_bounds__(TILE, 8) fused_kernel(
    const float* __restrict__ x,
    const float* __restrict__ U_re, const float* __restrict__ U_im,
    const float* __restrict__ w_cls,
    const float* __restrict__ w_in,  const float* __restrict__ b_in,
    const float* __restrict__ scale_in, const float* __restrict__ shift_in,
    const float* __restrict__ Wc,    const float* __restrict__ bc,
    const float* __restrict__ scalec, const float* __restrict__ shiftc,
    const float* __restrict__ w_out, const float* __restrict__ b_out,
    const float* __restrict__ b_cls,
    float* __restrict__ out, int B, int Lc)
{
    __shared__ float xs[TILE * 29];                 // 28 floats/img chunk, odd stride
    __shared__ __align__(16) float scratch[2112];   // 8448 B, phase-aliased
    __shared__ int s_old;

    const int t    = threadIdx.x;
    const int bx   = blockIdx.x;
    const int gy   = blockIdx.y;                    // 0..27
    const int rg   = gy >> 1;                       // patch-row group 0..13
    const int half = gy & 1;                        // which 7-patch half
    const int b0   = bx * TILE;

    float* urs = scratch;
    float* uis = scratch + 256;
    float* Hs  = scratch + 512;      // [w*256 + r*16 + c]
    float* T1  = scratch + 1536;     // [w*144 + m*16 + bb]
    float* Nbs = scratch;            // [ (w*9+m)*10 + n ], n=9 padded 0
    u64*   Ms  = (u64*)(scratch + 512);  // [pcl*54 + m*6 + np], 7 matrices

    const int nimg = min(TILE, B - b0);

    // ---- stage this block's 7-patch pixel chunk + U ----
    {
        const int rb = rg * 56 + 14 * half;         // row 2rg, col 14*half
        for (int i = t; i < nimg * 28; i += TILE) {
            const int img = i / 28, c = i - img * 28;
            const int src = (c < 14) ? (rb + c) : (rb + 28 + (c - 14));
            xs[img * 29 + c] = x[(size_t)(b0 + img) * 784 + src];
        }
    }
    for (int i = t; i < 256; i += TILE) { urs[i] = U_re[i]; uis[i] = U_im[i]; }
    __syncthreads();

    // ---- P2: H_w[r][c] (symmetric, 136 unique entries, Walsh signs) ----
    for (int e = t; e < 136; e += TILE) {
        int r = 0;
        while (e >= TRI_BASE[r + 1]) r++;
        const int c = r + (e - TRI_BASE[r]);
        float h0 = 0.f, h1 = 0.f, h2 = 0.f, h3 = 0.f;
        #pragma unroll
        for (int k = 0; k < 16; k++) {
            float pr = urs[k * 16 + r] * urs[k * 16 + c]
                     + uis[k * 16 + r] * uis[k * 16 + c];
            h0 += (k & 8) ? -pr : pr;
            h1 += (k & 4) ? -pr : pr;
            h2 += (k & 2) ? -pr : pr;
            h3 += (k & 1) ? -pr : pr;
        }
        Hs[0 * 256 + r * 16 + c] = h0;  Hs[0 * 256 + c * 16 + r] = h0;
        Hs[1 * 256 + r * 16 + c] = h1;  Hs[1 * 256 + c * 16 + r] = h1;
        Hs[2 * 256 + r * 16 + c] = h2;  Hs[2 * 256 + c * 16 + r] = h2;
        Hs[3 * 256 + r * 16 + c] = h3;  Hs[3 * 256 + c * 16 + r] = h3;
    }
    __syncthreads();

    // ---- P3: contract (a1,a2) -> m (4 sparse terms each) ----
    for (int e = t; e < 576; e += TILE) {
        const int w = e / 144, rem = e % 144, m = rem >> 4, bb = rem & 15;
        const int b1 = bb >> 2, b2 = bb & 3;
        float acc = 0.f;
        #pragma unroll
        for (int q = 0; q < 4; q++) {
            const int aa = CAA[m][q], a1 = aa >> 2, a2 = aa & 3;
            acc = fmaf(CSG[m][q], Hs[w * 256 + (4 * a1 + b1) * 16 + 4 * a2 + b2], acc);
        }
        T1[w * 144 + m * 16 + bb] = acc;
    }
    __syncthreads();

    // ---- P4: contract (b1,b2) -> n, scale 1/16, pad n=9 with 0 ----
    for (int e = t; e < 360; e += TILE) {
        const int w = e / 90, rem = e % 90, m = rem / 10, n = rem % 10;
        float acc = 0.f;
        if (n < 9) {
            #pragma unroll
            for (int q = 0; q < 4; q++)
                acc = fmaf(CSG[n][q], T1[w * 144 + m * 16 + CAA[n][q]], acc);
            acc *= 0.0625f;
        }
        Nbs[e] = acc;
    }
    __syncthreads();

    // ---- P5: fold w_cls into THIS block's 7 per-patch matrices ----
    for (int e = t; e < 7 * 45; e += TILE) {
        const int pcl = e / 45, r = e % 45, m = r / 5, np = r % 5;
        const float* wc = w_cls + 1 + 4 * (rg * 14 + 7 * half + pcl);
        float lo = 0.f, hi = 0.f;
        #pragma unroll
        for (int w = 0; w < 4; w++) {
            const float wcv = __ldg(wc + w);
            lo = fmaf(wcv, Nbs[(w * 9 + m) * 10 + 2 * np],     lo);
            hi = fmaf(wcv, Nbs[(w * 9 + m) * 10 + 2 * np + 1], hi);
        }
        Ms[pcl * 54 + m * 6 + np] = pack2(lo, hi);
    }
    __syncthreads();

    // ---- main loop: 7 patches; 9x9 bilinear form each ----
    if (t < nimg) {
        u64 s2 = 0ull, sq2 = 0ull;                  // packed mean/sumsq partials
        float C = 0.f;
        const float* xt = xs + t * 29;

        #pragma unroll 1
        for (int pcl = 0; pcl < 7; pcl++) {
            const float p0 = xt[2 * pcl],      p1 = xt[2 * pcl + 1];
            const float p2 = xt[14 + 2 * pcl], p3 = xt[15 + 2 * pcl];
            const u64 x01 = pack2(p0, p1), x23 = pack2(p2, p3);
            s2  = add2(s2, add2(x01, x23));
            sq2 = fma2(x01, x01, fma2(x23, x23, sq2));

            float sn0, cs0, sn1, cs1, sn2, cs2, sn3, cs3;
            __sincosf(p0, &sn0, &cs0);
            __sincosf(p1, &sn1, &cs1);
            __sincosf(p2, &sn2, &cs2);
            __sincosf(p3, &sn3, &cs3);

            // u = (1,c1,s1,c0,c0c1,c0s1,s0,s0c1,s0s1); v likewise on p2,p3
            const float u4 = cs0 * cs1, u5 = cs0 * sn1, u7 = sn0 * cs1, u8 = sn0 * sn1;
            const float v4 = cs2 * cs3, v5 = cs2 * sn3, v7 = sn2 * cs3, v8 = sn2 * sn3;
            const u64 vp0 = pack2(1.f, cs3), vp1 = pack2(sn3, cs2);
            const u64 vp2 = pack2(v4, v5),   vp3 = pack2(sn2, v7);
            const u64 vp4 = pack2(v8, 0.f);
            const float us[9] = {1.f, cs1, sn1, cs0, u4, u5, sn0, u7, u8};

            const u64* Mp = Ms + pcl * 54;
            u64 c2a = 0ull, c2b = 0ull;
            #pragma unroll
            for (int m = 0; m < 9; m++) {
                const ulonglong2* row = (const ulonglong2*)(Mp + m * 6);
                const ulonglong2 e01 = row[0];         // np 0,1 (broadcast LDS.128)
                const ulonglong2 e23 = row[1];         // np 2,3
                u64 y = mul2(e01.x, vp0);
                y = fma2(e01.y, vp1, y);
                y = fma2(e23.x, vp2, y);
                y = fma2(e23.y, vp3, y);
                y = fma2(Mp[m * 6 + 4], vp4, y);       // np 4 (v8, 0)
                const u64 uu = pack2(us[m], us[m]);
                if (m & 1) c2b = fma2(y, uu, c2b);
                else       c2a = fma2(y, uu, c2a);
            }
            const float2 cc = unpack2(add2(c2a, c2b));
            C += cc.x + cc.y;
        }

        const float2 sv = unpack2(s2);
        const float2 qv = unpack2(sq2);
        const int b = b0 + t;
        g_part[gy * B + b]        = sv.x + sv.y;
        g_part[(28 + gy) * B + b] = qv.x + qv.y;
        g_part[(56 + gy) * B + b] = C;
    }

    // ---- last-block-done finisher (28 blocks per image tile) ----
    __syncthreads();
    if (t == 0) {
        __threadfence();
        s_old = atomicAdd(&g_cnt[bx], 1);
    }
    __syncthreads();
    if (s_old != 27) return;

    if (t == 0) g_cnt[bx] = 0;        // reset for next launch / graph replay
    if (t >= nimg) return;

    const int b = b0 + t;
    float S = 0.f, Q = 0.f, Cq = 0.f;
    #pragma unroll
    for (int r = 0; r < 28; r++) {
        S  += g_part[r * B + b];
        Q  += g_part[(28 + r) * B + b];
        Cq += g_part[(56 + r) * B + b];
    }
    float mean = S * (1.f / 784.f);
    float var  = (Q - S * S * (1.f / 784.f)) * (1.f / 783.f);   // ddof=1
    float sd   = sqrtf(fmaxf(var, 0.f));
    float h0 = tanhf(mean * w_in[0] + sd * w_in[1] + b_in[0]) * scale_in[0] + shift_in[0];
    float h1 = tanhf(mean * w_in[2] + sd * w_in[3] + b_in[1]) * scale_in[1] + shift_in[1];
    for (int l = 0; l < Lc; l++) {
        float n0 = tanhf(h0 * Wc[l*4+0] + h1 * Wc[l*4+1] + bc[l*2+0]) * scalec[l*2+0] + shiftc[l*2+0];
        float n1 = tanhf(h0 * Wc[l*4+2] + h1 * Wc[l*4+3] + bc[l*2+1]) * scalec[l*2+1] + shiftc[l*2+1];
        h0 = n0; h1 = n1;
    }
    float cls   = h0 * w_out[0] + h1 * w_out[1] + b_out[0];
    float logit = b_cls[0] + cls * w_cls[0] + Cq;
    out[b] = 1.f / (1.f + __expf(-logit));
}

extern "C" void kernel_launch(void* const* d_in, const int* in_sizes, int n_in,
                              void* d_out, int out_size)
{
    const float* x        = (const float*)d_in[0];
    const float* w_in     = (const float*)d_in[1];
    const float* b_in     = (const float*)d_in[2];
    const float* scale_in = (const float*)d_in[3];
    const float* shift_in = (const float*)d_in[4];
    const float* Wc       = (const float*)d_in[5];
    const float* bc       = (const float*)d_in[6];
    const float* scalec   = (const float*)d_in[7];
    const float* shiftc   = (const float*)d_in[8];
    const float* w_out    = (const float*)d_in[9];
    const float* b_out    = (const float*)d_in[10];
    const float* U_re     = (const float*)d_in[11];
    const float* U_im     = (const float*)d_in[12];
    const float* w_cls    = (const float*)d_in[13];
    const float* b_cls    = (const float*)d_in[14];
    float* out = (float*)d_out;

    const int B  = in_sizes[0] / 784;   // (B,1,28,28)
    const int Lc = in_sizes[5] / 4;     // (L,2,2)

    dim3 grid((B + TILE - 1) / TILE, 28);
    fused_kernel<<<grid, TILE>>>(x, U_re, U_im, w_cls,
                                 w_in, b_in, scale_in, shift_in,
                                 Wc, bc, scalec, shiftc, w_out, b_out,
                                 b_cls, out, B, Lc);
}

// round 14
// speedup vs baseline: 1.2144x; 1.1309x over previous
#include <cuda_runtime.h>
#include <math.h>

typedef unsigned long long u64;

// ---- packed f32x2 helpers (sm_103a; ptxas won't auto-fuse) ----
__device__ __forceinline__ u64 pack2(float x, float y) {
    u64 r; asm("mov.b64 %0, {%1, %2};" : "=l"(r) : "f"(x), "f"(y)); return r;
}
__device__ __forceinline__ u64 fma2(u64 a, u64 b, u64 c) {
    u64 d; asm("fma.rn.f32x2 %0, %1, %2, %3;" : "=l"(d) : "l"(a), "l"(b), "l"(c)); return d;
}
__device__ __forceinline__ u64 mul2(u64 a, u64 b) {
    u64 d; asm("mul.rn.f32x2 %0, %1, %2;" : "=l"(d) : "l"(a), "l"(b)); return d;
}
__device__ __forceinline__ u64 add2(u64 a, u64 b) {
    u64 d; asm("add.rn.f32x2 %0, %1, %2;" : "=l"(d) : "l"(a), "l"(b)); return d;
}
__device__ __forceinline__ float2 unpack2(u64 v) {
    float x, y; asm("mov.b64 {%0, %1}, %2;" : "=f"(x), "=f"(y) : "l"(v)); return make_float2(x, y);
}

#define MAXB 8192
#define TILE 128

// per-(row-group, image) partials: [0:14B) sum, [14B:28B) sumsq, [28B:42B) qdot
__device__ float g_part[3 * 14 * MAXB];
// per-image-tile completion counters (finisher resets to 0 -> replay-safe)
__device__ int g_cnt[(MAXB + TILE - 1) / TILE];

// Sparse trig-basis contraction: column m of the half->full angle map has
// exactly 4 nonzeros at pair-indices CAA[m][q] with signs CSG[m][q].
__constant__ int   CAA[9][4] = {
    {0,5,10,15}, {0,5,10,15}, {1,4,11,14}, {0,5,10,15}, {0,5,10,15},
    {1,4,11,14}, {2,7,8,13}, {2,7,8,13}, {3,6,9,12}};
__constant__ float CSG[9][4] = {
    {1,1,1,1}, {1,-1,1,-1}, {1,1,1,1}, {1,1,-1,-1}, {1,-1,-1,1},
    {1,1,-1,-1}, {1,1,1,1}, {1,-1,1,-1}, {1,1,1,1}};

// triangular row base: base[r] = r*16 - r(r-1)/2
__constant__ int TRI_BASE[17] = {0,16,31,45,58,70,81,91,100,108,115,121,126,130,133,135,136};

// ---------------------------------------------------------------------------
// Single fused kernel — the proven 25.1us geometry (block = 128 images x one
// patch-row group, xs staged once, grid (B/128, 14)), with the main patch
// loop software-pipelined (unroll 2) so each warp carries two independent
// LDS->MUFU->FFMA2 chains. launch_bounds(128,6) pins regs <= 85 so the
// unroll cannot drop residency below the grid-imposed 6 blocks/SM.
// ---------------------------------------------------------------------------
__global__ void __launch_bounds__(TILE, 6) fused_kernel(
    const float* __restrict__ x,
    const float* __restrict__ U_re, const float* __restrict__ U_im,
    const float* __restrict__ w_cls,
    const float* __restrict__ w_in,  const float* __restrict__ b_in,
    const float* __restrict__ scale_in, const float* __restrict__ shift_in,
    const float* __restrict__ Wc,    const float* __restrict__ bc,
    const float* __restrict__ scalec, const float* __restrict__ shiftc,
    const float* __restrict__ w_out, const float* __restrict__ b_out,
    const float* __restrict__ b_cls,
    float* __restrict__ out, int B, int Lc)
{
    __shared__ float xs[TILE * 57];                 // 57-pad: conflict-free rows
    __shared__ __align__(16) float scratch[2112];   // 8448 B, phase-aliased
    __shared__ int s_old;

    const int t  = threadIdx.x;
    const int bx = blockIdx.x;
    const int b0 = bx * TILE;
    const int rg = blockIdx.y;                      // 0..13

    float* urs = scratch;
    float* uis = scratch + 256;
    float* Hs  = scratch + 512;      // [w*256 + r*16 + c]
    float* T1  = scratch + 1536;     // [w*144 + m*16 + bb]
    float* Nbs = scratch;            // [ (w*9+m)*10 + n ], n=9 padded 0
    u64*   Ms  = (u64*)(scratch + 512);  // [pc*54 + m*6 + np]

    // ---- image tile + U load ----
    const int nimg = min(TILE, B - b0);
    const float* xb = x + (size_t)b0 * 784 + rg * 56;  // rows 2rg,2rg+1 contiguous
    for (int i = t; i < nimg * 56; i += TILE) {
        int img = i / 56, c = i - img * 56;
        xs[img * 57 + c] = xb[(size_t)img * 784 + c];
    }
    for (int i = t; i < 256; i += TILE) { urs[i] = U_re[i]; uis[i] = U_im[i]; }
    __syncthreads();

    // ---- P2: H_w[r][c] (symmetric, 136 unique entries, Walsh signs) ----
    for (int e = t; e < 136; e += TILE) {
        int r = 0;
        while (e >= TRI_BASE[r + 1]) r++;
        const int c = r + (e - TRI_BASE[r]);
        float h0 = 0.f, h1 = 0.f, h2 = 0.f, h3 = 0.f;
        #pragma unroll
        for (int k = 0; k < 16; k++) {
            float pr = urs[k * 16 + r] * urs[k * 16 + c]
                     + uis[k * 16 + r] * uis[k * 16 + c];
            h0 += (k & 8) ? -pr : pr;
            h1 += (k & 4) ? -pr : pr;
            h2 += (k & 2) ? -pr : pr;
            h3 += (k & 1) ? -pr : pr;
        }
        Hs[0 * 256 + r * 16 + c] = h0;  Hs[0 * 256 + c * 16 + r] = h0;
        Hs[1 * 256 + r * 16 + c] = h1;  Hs[1 * 256 + c * 16 + r] = h1;
        Hs[2 * 256 + r * 16 + c] = h2;  Hs[2 * 256 + c * 16 + r] = h2;
        Hs[3 * 256 + r * 16 + c] = h3;  Hs[3 * 256 + c * 16 + r] = h3;
    }
    __syncthreads();

    // ---- P3: contract (a1,a2) -> m (4 sparse terms each) ----
    for (int e = t; e < 576; e += TILE) {
        const int w = e / 144, rem = e % 144, m = rem >> 4, bb = rem & 15;
        const int b1 = bb >> 2, b2 = bb & 3;
        float acc = 0.f;
        #pragma unroll
        for (int q = 0; q < 4; q++) {
            const int aa = CAA[m][q], a1 = aa >> 2, a2 = aa & 3;
            acc = fmaf(CSG[m][q], Hs[w * 256 + (4 * a1 + b1) * 16 + 4 * a2 + b2], acc);
        }
        T1[w * 144 + m * 16 + bb] = acc;
    }
    __syncthreads();

    // ---- P4: contract (b1,b2) -> n, scale 1/16, pad n=9 with 0 ----
    for (int e = t; e < 360; e += TILE) {
        const int w = e / 90, rem = e % 90, m = rem / 10, n = rem % 10;
        float acc = 0.f;
        if (n < 9) {
            #pragma unroll
            for (int q = 0; q < 4; q++)
                acc = fmaf(CSG[n][q], T1[w * 144 + m * 16 + CAA[n][q]], acc);
            acc *= 0.0625f;
        }
        Nbs[e] = acc;
    }
    __syncthreads();

    // ---- P5: fold w_cls into 14 per-patch matrices ----
    for (int e = t; e < 14 * 45; e += TILE) {
        const int pc = e / 45, r = e % 45, m = r / 5, np = r % 5;
        const float* wc = w_cls + 1 + 4 * (rg * 14 + pc);
        float lo = 0.f, hi = 0.f;
        #pragma unroll
        for (int w = 0; w < 4; w++) {
            const float wcv = __ldg(wc + w);
            lo = fmaf(wcv, Nbs[(w * 9 + m) * 10 + 2 * np],     lo);
            hi = fmaf(wcv, Nbs[(w * 9 + m) * 10 + 2 * np + 1], hi);
        }
        Ms[pc * 54 + m * 6 + np] = pack2(lo, hi);
    }
    __syncthreads();

    // ---- main loop: 9x9 bilinear form per patch, 2-way software pipeline ----
    if (t < nimg) {
        u64 s2 = 0ull, sq2 = 0ull;                  // packed mean/sumsq partials
        float C = 0.f;
        const float* xt = xs + t * 57;

        #pragma unroll 2
        for (int pc = 0; pc < 14; pc++) {
            const float p0 = xt[2 * pc], p1 = xt[2 * pc + 1];
            const float p2 = xt[28 + 2 * pc], p3 = xt[29 + 2 * pc];
            const u64 x01 = pack2(p0, p1), x23 = pack2(p2, p3);
            s2  = add2(s2, add2(x01, x23));
            sq2 = fma2(x01, x01, fma2(x23, x23, sq2));

            float sn0, cs0, sn1, cs1, sn2, cs2, sn3, cs3;
            __sincosf(p0, &sn0, &cs0);
            __sincosf(p1, &sn1, &cs1);
            __sincosf(p2, &sn2, &cs2);
            __sincosf(p3, &sn3, &cs3);

            // u = (1, c1, s1, c0, c0c1, c0s1, s0, s0c1, s0s1); v likewise on p2,p3
            const float u4 = cs0 * cs1, u5 = cs0 * sn1, u7 = sn0 * cs1, u8 = sn0 * sn1;
            const float v4 = cs2 * cs3, v5 = cs2 * sn3, v7 = sn2 * cs3, v8 = sn2 * sn3;
            const u64 vp0 = pack2(1.f, cs3), vp1 = pack2(sn3, cs2);
            const u64 vp2 = pack2(v4, v5),   vp3 = pack2(sn2, v7);
            const u64 vp4 = pack2(v8, 0.f);
            const float us[9] = {1.f, cs1, sn1, cs0, u4, u5, sn0, u7, u8};

            const u64* Mp = Ms + pc * 54;
            u64 c2a = 0ull, c2b = 0ull;
            #pragma unroll
            for (int m = 0; m < 9; m++) {
                const ulonglong2* row = (const ulonglong2*)(Mp + m * 6);
                const ulonglong2 e01 = row[0];         // np 0,1 (broadcast LDS.128)
                const ulonglong2 e23 = row[1];         // np 2,3
                u64 y = mul2(e01.x, vp0);
                y = fma2(e01.y, vp1, y);
                y = fma2(e23.x, vp2, y);
                y = fma2(e23.y, vp3, y);
                y = fma2(Mp[m * 6 + 4], vp4, y);       // np 4 (v8, 0)
                const u64 uu = pack2(us[m], us[m]);
                if (m & 1) c2b = fma2(y, uu, c2b);
                else       c2a = fma2(y, uu, c2a);
            }
            const float2 cc = unpack2(add2(c2a, c2b));
            C += cc.x + cc.y;
        }

        const float2 sv = unpack2(s2);
        const float2 qv = unpack2(sq2);
        const int b = b0 + t;
        g_part[rg * B + b]        = sv.x + sv.y;
        g_part[(14 + rg) * B + b] = qv.x + qv.y;
        g_part[(28 + rg) * B + b] = C;
    }

    // ---- last-block-done finisher ----
    __syncthreads();
    if (t == 0) {
        __threadfence();
        s_old = atomicAdd(&g_cnt[bx], 1);
    }
    __syncthreads();
    if (s_old != 13) return;

    if (t == 0) g_cnt[bx] = 0;        // reset for next launch / graph replay
    if (t >= nimg) return;

    const int b = b0 + t;
    float S = 0.f, Q = 0.f, Cq = 0.f;
    #pragma unroll
    for (int r = 0; r < 14; r++) {
        S  += g_part[r * B + b];
        Q  += g_part[(14 + r) * B + b];
        Cq += g_part[(28 + r) * B + b];
    }
    float mean = S * (1.f / 784.f);
    float var  = (Q - S * S * (1.f / 784.f)) * (1.f / 783.f);   // ddof=1
    float sd   = sqrtf(fmaxf(var, 0.f));
    float h0 = tanhf(mean * w_in[0] + sd * w_in[1] + b_in[0]) * scale_in[0] + shift_in[0];
    float h1 = tanhf(mean * w_in[2] + sd * w_in[3] + b_in[1]) * scale_in[1] + shift_in[1];
    for (int l = 0; l < Lc; l++) {
        float n0 = tanhf(h0 * Wc[l*4+0] + h1 * Wc[l*4+1] + bc[l*2+0]) * scalec[l*2+0] + shiftc[l*2+0];
        float n1 = tanhf(h0 * Wc[l*4+2] + h1 * Wc[l*4+3] + bc[l*2+1]) * scalec[l*2+1] + shiftc[l*2+1];
        h0 = n0; h1 = n1;
    }
    float cls   = h0 * w_out[0] + h1 * w_out[1] + b_out[0];
    float logit = b_cls[0] + cls * w_cls[0] + Cq;
    out[b] = 1.f / (1.f + __expf(-logit));
}

extern "C" void kernel_launch(void* const* d_in, const int* in_sizes, int n_in,
                              void* d_out, int out_size)
{
    const float* x        = (const float*)d_in[0];
    const float* w_in     = (const float*)d_in[1];
    const float* b_in     = (const float*)d_in[2];
    const float* scale_in = (const float*)d_in[3];
    const float* shift_in = (const float*)d_in[4];
    const float* Wc       = (const float*)d_in[5];
    const float* bc       = (const float*)d_in[6];
    const float* scalec   = (const float*)d_in[7];
    const float* shiftc   = (const float*)d_in[8];
    const float* w_out    = (const float*)d_in[9];
    const float* b_out    = (const float*)d_in[10];
    const float* U_re     = (const float*)d_in[11];
    const float* U_im     = (const float*)d_in[12];
    const float* w_cls    = (const float*)d_in[13];
    const float* b_cls    = (const float*)d_in[14];
    float* out = (float*)d_out;

    const int B  = in_sizes[0] / 784;   // (B,1,28,28)
    const int Lc = in_sizes[5] / 4;     // (L,2,2)

    dim3 grid((B + TILE - 1) / TILE, 14);
    fused_kernel<<<grid, TILE>>>(x, U_re, U_im, w_cls,
                                 w_in, b_in, scale_in, shift_in,
                                 Wc, bc, scalec, shiftc, w_out, b_out,
                                 b_cls, out, B, Lc);
}

// round 16
// speedup vs baseline: 1.3266x; 1.0924x over previous
#include <cuda_runtime.h>
#include <math.h>

typedef unsigned long long u64;

// ---- packed f32x2 helpers (sm_103a; ptxas won't auto-fuse) ----
__device__ __forceinline__ u64 pack2(float x, float y) {
    u64 r; asm("mov.b64 %0, {%1, %2};" : "=l"(r) : "f"(x), "f"(y)); return r;
}
__device__ __forceinline__ u64 fma2(u64 a, u64 b, u64 c) {
    u64 d; asm("fma.rn.f32x2 %0, %1, %2, %3;" : "=l"(d) : "l"(a), "l"(b), "l"(c)); return d;
}
__device__ __forceinline__ u64 mul2(u64 a, u64 b) {
    u64 d; asm("mul.rn.f32x2 %0, %1, %2;" : "=l"(d) : "l"(a), "l"(b)); return d;
}
__device__ __forceinline__ u64 add2(u64 a, u64 b) {
    u64 d; asm("add.rn.f32x2 %0, %1, %2;" : "=l"(d) : "l"(a), "l"(b)); return d;
}
__device__ __forceinline__ float2 unpack2(u64 v) {
    float x, y; asm("mov.b64 {%0, %1}, %2;" : "=f"(x), "=f"(y) : "l"(v)); return make_float2(x, y);
}

#define MAXB 8192
#define TILE 128

// per-(row-group, image) partials: [0:14B) sum, [14B:28B) sumsq, [28B:42B) qdot
__device__ float g_part[3 * 14 * MAXB];
// per-image-tile completion counters (finisher resets to 0 -> replay-safe)
__device__ int g_cnt[(MAXB + TILE - 1) / TILE];

// Sparse trig-basis contraction: column m of the half->full angle map has
// exactly 4 nonzeros at pair-indices CAA[m][q] with signs CSG[m][q].
__constant__ int   CAA[9][4] = {
    {0,5,10,15}, {0,5,10,15}, {1,4,11,14}, {0,5,10,15}, {0,5,10,15},
    {1,4,11,14}, {2,7,8,13}, {2,7,8,13}, {3,6,9,12}};
__constant__ float CSG[9][4] = {
    {1,1,1,1}, {1,-1,1,-1}, {1,1,1,1}, {1,1,-1,-1}, {1,-1,-1,1},
    {1,1,-1,-1}, {1,1,1,1}, {1,-1,1,-1}, {1,1,1,1}};

// triangular row base: base[r] = r*16 - r(r-1)/2
__constant__ int TRI_BASE[17] = {0,16,31,45,58,70,81,91,100,108,115,121,126,130,133,135,136};

// ---------------------------------------------------------------------------
// Single fused kernel, R8 geometry (block = 128 images x one patch-row
// group, grid (B/128, 14)), but the main loop processes PATCH PAIRS
// (pc, pc+7) packed in the two f32x2 lanes: matvec/dot/u/v all pair-packed,
// cutting main-loop fma2 count ~25% and LDS ~17% per patch.
// M storage: Ms2[(pc*9+m)*10 + n] = ( M_{pc}[m][n], M_{pc+7}[m][n] ),
// n=9 is zero padding so each m-row is 5 aligned LDS.128.
// ---------------------------------------------------------------------------
__global__ void __launch_bounds__(TILE, 6) fused_kernel(
    const float* __restrict__ x,
    const float* __restrict__ U_re, const float* __restrict__ U_im,
    const float* __restrict__ w_cls,
    const float* __restrict__ w_in,  const float* __restrict__ b_in,
    const float* __restrict__ scale_in, const float* __restrict__ shift_in,
    const float* __restrict__ Wc,    const float* __restrict__ bc,
    const float* __restrict__ scalec, const float* __restrict__ shiftc,
    const float* __restrict__ w_out, const float* __restrict__ b_out,
    const float* __restrict__ b_cls,
    float* __restrict__ out, int B, int Lc)
{
    __shared__ float xs[TILE * 57];                 // 57-pad: conflict-free rows
    __shared__ __align__(16) float scratch[2112];   // 8448 B, phase-aliased
    __shared__ int s_old;

    const int t  = threadIdx.x;
    const int bx = blockIdx.x;
    const int b0 = bx * TILE;
    const int rg = blockIdx.y;                      // 0..13

    float* urs = scratch;
    float* uis = scratch + 256;
    float* Hs  = scratch + 512;      // [w*256 + r*16 + c]
    float* T1  = scratch + 1536;     // [w*144 + m*16 + bb]
    float* Nbs = scratch;            // [ (w*9+m)*10 + n ], n=9 padded 0
    u64*   Ms2 = (u64*)(scratch + 512);  // [(pc*9+m)*10 + n], 630 u64 (5 KB)

    // ---- image tile + U load ----
    const int nimg = min(TILE, B - b0);
    const float* xb = x + (size_t)b0 * 784 + rg * 56;  // rows 2rg,2rg+1 contiguous
    for (int i = t; i < nimg * 56; i += TILE) {
        int img = i / 56, c = i - img * 56;
        xs[img * 57 + c] = xb[(size_t)img * 784 + c];
    }
    for (int i = t; i < 256; i += TILE) { urs[i] = U_re[i]; uis[i] = U_im[i]; }
    __syncthreads();

    // ---- P2: H_w[r][c] (symmetric, 136 unique entries, Walsh signs) ----
    for (int e = t; e < 136; e += TILE) {
        int r = 0;
        while (e >= TRI_BASE[r + 1]) r++;
        const int c = r + (e - TRI_BASE[r]);
        float h0 = 0.f, h1 = 0.f, h2 = 0.f, h3 = 0.f;
        #pragma unroll
        for (int k = 0; k < 16; k++) {
            float pr = urs[k * 16 + r] * urs[k * 16 + c]
                     + uis[k * 16 + r] * uis[k * 16 + c];
            h0 += (k & 8) ? -pr : pr;
            h1 += (k & 4) ? -pr : pr;
            h2 += (k & 2) ? -pr : pr;
            h3 += (k & 1) ? -pr : pr;
        }
        Hs[0 * 256 + r * 16 + c] = h0;  Hs[0 * 256 + c * 16 + r] = h0;
        Hs[1 * 256 + r * 16 + c] = h1;  Hs[1 * 256 + c * 16 + r] = h1;
        Hs[2 * 256 + r * 16 + c] = h2;  Hs[2 * 256 + c * 16 + r] = h2;
        Hs[3 * 256 + r * 16 + c] = h3;  Hs[3 * 256 + c * 16 + r] = h3;
    }
    __syncthreads();

    // ---- P3: contract (a1,a2) -> m (4 sparse terms each) ----
    for (int e = t; e < 576; e += TILE) {
        const int w = e / 144, rem = e % 144, m = rem >> 4, bb = rem & 15;
        const int b1 = bb >> 2, b2 = bb & 3;
        float acc = 0.f;
        #pragma unroll
        for (int q = 0; q < 4; q++) {
            const int aa = CAA[m][q], a1 = aa >> 2, a2 = aa & 3;
            acc = fmaf(CSG[m][q], Hs[w * 256 + (4 * a1 + b1) * 16 + 4 * a2 + b2], acc);
        }
        T1[w * 144 + m * 16 + bb] = acc;
    }
    __syncthreads();

    // ---- P4: contract (b1,b2) -> n, scale 1/16, pad n=9 with 0 ----
    for (int e = t; e < 360; e += TILE) {
        const int w = e / 90, rem = e % 90, m = rem / 10, n = rem % 10;
        float acc = 0.f;
        if (n < 9) {
            #pragma unroll
            for (int q = 0; q < 4; q++)
                acc = fmaf(CSG[n][q], T1[w * 144 + m * 16 + CAA[n][q]], acc);
            acc *= 0.0625f;
        }
        Nbs[e] = acc;
    }
    __syncthreads();

    // ---- P5: fold w_cls into 7 patch-PAIR matrices (lanes = pc, pc+7) ----
    for (int e = t; e < 630; e += TILE) {
        const int pc = e / 90, rem = e % 90, m = rem / 10, n = rem % 10;
        float lo = 0.f, hi = 0.f;
        if (n < 9) {
            const float* wca = w_cls + 1 + 4 * (rg * 14 + pc);
            const float* wcb = w_cls + 1 + 4 * (rg * 14 + pc + 7);
            #pragma unroll
            for (int w = 0; w < 4; w++) {
                const float nb = Nbs[(w * 9 + m) * 10 + n];
                lo = fmaf(__ldg(wca + w), nb, lo);
                hi = fmaf(__ldg(wcb + w), nb, hi);
            }
        }
        Ms2[e] = pack2(lo, hi);
    }
    __syncthreads();

    // ---- main loop: 7 patch pairs; pair-packed 9x9 bilinear form ----
    if (t < nimg) {
        u64 s2 = 0ull, sq2 = 0ull;                  // packed mean/sumsq partials
        float C = 0.f;
        const float* xt = xs + t * 57;

        #pragma unroll 1
        for (int pc = 0; pc < 7; pc++) {
            // patch a = pc (cols 2pc,2pc+1), patch b = pc+7 (cols 14+2pc,15+2pc)
            const float a0 = xt[2 * pc],       a1 = xt[2 * pc + 1];
            const float a2 = xt[28 + 2 * pc],  a3 = xt[29 + 2 * pc];
            const float bb0 = xt[14 + 2 * pc], bb1 = xt[15 + 2 * pc];
            const float bb2 = xt[42 + 2 * pc], bb3 = xt[43 + 2 * pc];

            const u64 xA = pack2(a0, a1),  xB = pack2(a2, a3);
            const u64 xC = pack2(bb0, bb1), xD = pack2(bb2, bb3);
            s2  = add2(s2, add2(add2(xA, xB), add2(xC, xD)));
            sq2 = fma2(xA, xA, fma2(xB, xB, fma2(xC, xC, fma2(xD, xD, sq2))));

            float sa0, ca0, sa1, ca1, sa2, ca2, sa3, ca3;
            float sb0, cb0, sb1, cb1, sb2, cb2, sb3, cb3;
            __sincosf(a0,  &sa0, &ca0);  __sincosf(a1,  &sa1, &ca1);
            __sincosf(a2,  &sa2, &ca2);  __sincosf(a3,  &sa3, &ca3);
            __sincosf(bb0, &sb0, &cb0);  __sincosf(bb1, &sb1, &cb1);
            __sincosf(bb2, &sb2, &cb2);  __sincosf(bb3, &sb3, &cb3);

            // pair-packed trig: lane0 = patch a, lane1 = patch b
            const u64 c0p = pack2(ca0, cb0), s0p = pack2(sa0, sb0);
            const u64 c1p = pack2(ca1, cb1), s1p = pack2(sa1, sb1);
            const u64 c2p = pack2(ca2, cb2), s2p = pack2(sa2, sb2);
            const u64 c3p = pack2(ca3, cb3), s3p = pack2(sa3, sb3);

            // u = (1, c1, s1, c0, c0c1, c0s1, s0, s0c1, s0s1); v same on angles 2,3
            const u64 u1 = c1p, u2 = s1p, u3 = c0p;
            const u64 u4 = mul2(c0p, c1p), u5 = mul2(c0p, s1p);
            const u64 u6 = s0p;
            const u64 u7 = mul2(s0p, c1p), u8 = mul2(s0p, s1p);
            const u64 v1 = c3p, v2 = s3p, v3 = c2p;
            const u64 v4 = mul2(c2p, c3p), v5 = mul2(c2p, s3p);
            const u64 v6 = s2p;
            const u64 v7 = mul2(s2p, c3p), v8 = mul2(s2p, s3p);

            const u64* Mp = Ms2 + pc * 90;
            u64 c2acc0 = 0ull, c2acc1 = 0ull;
            #pragma unroll
            for (int m = 0; m < 9; m++) {
                const ulonglong2* row = (const ulonglong2*)(Mp + m * 10);
                const ulonglong2 r0 = row[0];   // n=0,1   (broadcast LDS.128)
                const ulonglong2 r1 = row[1];   // n=2,3
                const ulonglong2 r2 = row[2];   // n=4,5
                const ulonglong2 r3 = row[3];   // n=6,7
                const ulonglong2 r4 = row[4];   // n=8,pad
                u64 y = r0.x;                    // v0 = 1
                y = fma2(r0.y, v1, y);
                y = fma2(r1.x, v2, y);
                y = fma2(r1.y, v3, y);
                y = fma2(r2.x, v4, y);
                y = fma2(r2.y, v5, y);
                y = fma2(r3.x, v6, y);
                y = fma2(r3.y, v7, y);
                y = fma2(r4.x, v8, y);
                // dot with u_m (u0 = 1)
                u64 um;
                switch (m) {
                    case 0: um = 0ull; break;   // handled as add below
                    case 1: um = u1; break;  case 2: um = u2; break;
                    case 3: um = u3; break;  case 4: um = u4; break;
                    case 5: um = u5; break;  case 6: um = u6; break;
                    case 7: um = u7; break;  default: um = u8; break;
                }
                if (m == 0)      c2acc0 = add2(c2acc0, y);
                else if (m & 1)  c2acc1 = fma2(y, um, c2acc1);
                else             c2acc0 = fma2(y, um, c2acc0);
            }
            const float2 cc = unpack2(add2(c2acc0, c2acc1));
            C += cc.x + cc.y;                   // both patches of the pair
        }

        const float2 sv = unpack2(s2);
        const float2 qv = unpack2(sq2);
        const int b = b0 + t;
        g_part[rg * B + b]        = sv.x + sv.y;
        g_part[(14 + rg) * B + b] = qv.x + qv.y;
        g_part[(28 + rg) * B + b] = C;
    }

    // ---- last-block-done finisher ----
    __syncthreads();
    if (t == 0) {
        __threadfence();
        s_old = atomicAdd(&g_cnt[bx], 1);
    }
    __syncthreads();
    if (s_old != 13) return;

    if (t == 0) g_cnt[bx] = 0;        // reset for next launch / graph replay
    if (t >= nimg) return;

    const int b = b0 + t;
    float S = 0.f, Q = 0.f, Cq = 0.f;
    #pragma unroll
    for (int r = 0; r < 14; r++) {
        S  += g_part[r * B + b];
        Q  += g_part[(14 + r) * B + b];
        Cq += g_part[(28 + r) * B + b];
    }
    float mean = S * (1.f / 784.f);
    float var  = (Q - S * S * (1.f / 784.f)) * (1.f / 783.f);   // ddof=1
    float sd   = sqrtf(fmaxf(var, 0.f));
    float h0 = tanhf(mean * w_in[0] + sd * w_in[1] + b_in[0]) * scale_in[0] + shift_in[0];
    float h1 = tanhf(mean * w_in[2] + sd * w_in[3] + b_in[1]) * scale_in[1] + shift_in[1];
    for (int l = 0; l < Lc; l++) {
        float n0 = tanhf(h0 * Wc[l*4+0] + h1 * Wc[l*4+1] + bc[l*2+0]) * scalec[l*2+0] + shiftc[l*2+0];
        float n1 = tanhf(h0 * Wc[l*4+2] + h1 * Wc[l*4+3] + bc[l*2+1]) * scalec[l*2+1] + shiftc[l*2+1];
        h0 = n0; h1 = n1;
    }
    float cls   = h0 * w_out[0] + h1 * w_out[1] + b_out[0];
    float logit = b_cls[0] + cls * w_cls[0] + Cq;
    out[b] = 1.f / (1.f + __expf(-logit));
}

extern "C" void kernel_launch(void* const* d_in, const int* in_sizes, int n_in,
                              void* d_out, int out_size)
{
    const float* x        = (const float*)d_in[0];
    const float* w_in     = (const float*)d_in[1];
    const float* b_in     = (const float*)d_in[2];
    const float* scale_in = (const float*)d_in[3];
    const float* shift_in = (const float*)d_in[4];
    const float* Wc       = (const float*)d_in[5];
    const float* bc       = (const float*)d_in[6];
    const float* scalec   = (const float*)d_in[7];
    const float* shiftc   = (const float*)d_in[8];
    const float* w_out    = (const float*)d_in[9];
    const float* b_out    = (const float*)d_in[10];
    const float* U_re     = (const float*)d_in[11];
    const float* U_im     = (const float*)d_in[12];
    const float* w_cls    = (const float*)d_in[13];
    const float* b_cls    = (const float*)d_in[14];
    float* out = (float*)d_out;

    const int B  = in_sizes[0] / 784;   // (B,1,28,28)
    const int Lc = in_sizes[5] / 4;     // (L,2,2)

    dim3 grid((B + TILE - 1) / TILE, 14);
    fused_kernel<<<grid, TILE>>>(x, U_re, U_im, w_cls,
                                 w_in, b_in, scale_in, shift_in,
                                 Wc, bc, scalec, shiftc, w_out, b_out,
                                 b_cls, out, B, Lc);
}